// round 6
// baseline (speedup 1.0000x reference)
#include <cuda_runtime.h>
#include <cstdint>
#include <cstddef>

#define NN 50000
#define NE 800000
#define SCAN_T 1024
#define SCAN_B ((NN + SCAN_T - 1) / SCAN_T)   // 49

// ---------------- static device scratch ----------------
__device__ float d_deg[NN];
__device__ float d_dinv[NN];
__device__ int   d_counts[NN];
__device__ int   d_scanned[NN];
__device__ int   d_scanblk[SCAN_B];
__device__ int   d_rowptr[NN + 1];
__device__ int   d_wp[NN];
__device__ int   d_csr_src[NE];
__device__ float d_csr_w[NE];
__device__ float d_h1[NN * 64];
__device__ float d_z[NN];
__device__ float d_smlp[NN];
__device__ float d_w2f[512];   // fc2_W @ fcf_W[0:64]
__device__ float d_vg[64];     // gcn2_W @ fcf_W[64:128]
__device__ float d_cmlp;       // fc2_b . fcf_W[0:64]
__device__ float d_cgnn;       // gcn2_b . fcf_W[64:128] + fcf_b

// ---------------- precompute collapsed vectors ----------------
__global__ void prep_vecs(const float* __restrict__ W2, const float* __restrict__ g2W,
                          const float* __restrict__ b2, const float* __restrict__ g2b,
                          const float* __restrict__ Wf, const float* __restrict__ fb) {
    int t = threadIdx.x;   // 512 threads
    float s = 0.f;
#pragma unroll 8
    for (int c = 0; c < 64; c++) s += W2[t * 64 + c] * Wf[c];
    d_w2f[t] = s;
    if (t < 64) {
        float s2 = 0.f;
#pragma unroll 8
        for (int c = 0; c < 64; c++) s2 += g2W[t * 64 + c] * Wf[64 + c];
        d_vg[t] = s2;
    }
    if (t == 0) {
        float cm = 0.f, cg = 0.f;
        for (int c = 0; c < 64; c++) { cm += b2[c] * Wf[c]; cg += g2b[c] * Wf[64 + c]; }
        d_cmlp = cm;
        d_cgnn = cg + fb[0];
    }
}

__global__ void zero_smlp() {
    int i = blockIdx.x * blockDim.x + threadIdx.x;
    if (i < NN) d_smlp[i] = 0.0f;
}

// ---------------- graph preprocessing ----------------
__global__ void init_nodes() {
    int i = blockIdx.x * blockDim.x + threadIdx.x;
    if (i < NN) { d_deg[i] = 1.0f; d_counts[i] = 0; }
}

__global__ void edge_deg_count(const int* __restrict__ src, const int* __restrict__ dst,
                               const float* __restrict__ ew) {
    int e = blockIdx.x * blockDim.x + threadIdx.x;
    if (e < NE) {
        int d = dst[e];
        atomicAdd(&d_deg[d], ew[e]);
        atomicAdd(&d_counts[d], 1);
    }
}

__global__ void compute_dinv() {
    int i = blockIdx.x * blockDim.x + threadIdx.x;
    if (i < NN) {
        float dg = d_deg[i];
        d_dinv[i] = (dg > 0.0f) ? rsqrtf(fmaxf(dg, 1e-12f)) : 0.0f;
    }
}

__global__ void scan_block() {
    __shared__ int s[SCAN_T];
    int tid = threadIdx.x;
    int i = blockIdx.x * SCAN_T + tid;
    int v = (i < NN) ? d_counts[i] : 0;
    s[tid] = v;
    __syncthreads();
#pragma unroll
    for (int off = 1; off < SCAN_T; off <<= 1) {
        int t = (tid >= off) ? s[tid - off] : 0;
        __syncthreads();
        s[tid] += t;
        __syncthreads();
    }
    if (i < NN) d_scanned[i] = s[tid];
    if (tid == SCAN_T - 1) d_scanblk[blockIdx.x] = s[tid];
}

__global__ void scan_top() {
    __shared__ int s[64];
    int tid = threadIdx.x;
    int v = (tid < SCAN_B) ? d_scanblk[tid] : 0;
    s[tid] = v;
    __syncthreads();
#pragma unroll
    for (int off = 1; off < 64; off <<= 1) {
        int t = (tid >= off) ? s[tid - off] : 0;
        __syncthreads();
        s[tid] += t;
        __syncthreads();
    }
    if (tid < SCAN_B) d_scanblk[tid] = (tid == 0) ? 0 : s[tid - 1];
}

__global__ void finalize_rowptr() {
    int i = blockIdx.x * blockDim.x + threadIdx.x;
    if (i < NN) {
        int incl = d_scanned[i] + d_scanblk[i >> 10];
        d_rowptr[i + 1] = incl;
        int excl = (i == 0) ? 0 : (d_scanned[i - 1] + d_scanblk[(i - 1) >> 10]);
        d_wp[i] = excl;
        if (i == 0) d_rowptr[0] = 0;
    }
}

__global__ void fill_csr(const int* __restrict__ src, const int* __restrict__ dst,
                         const float* __restrict__ ew) {
    int e = blockIdx.x * blockDim.x + threadIdx.x;
    if (e < NE) {
        int s = src[e];
        int d = dst[e];
        int pos = atomicAdd(&d_wp[d], 1);
        d_csr_src[pos] = s;
        d_csr_w[pos] = d_dinv[s] * ew[e] * d_dinv[d];
    }
}

// ---------------- GCN aggregation 1 + relu + z = g . vg ----------------
__global__ void gcn_agg1_z(const float* __restrict__ h, const float* __restrict__ bias,
                           float* __restrict__ z) {
    int gw = (blockIdx.x * blockDim.x + threadIdx.x) >> 5;
    int lane = threadIdx.x & 31;
    if (gw >= NN) return;
    int i = gw;
    float di = d_dinv[i];
    float selfw = di * di;
    float a0 = selfw * h[(size_t)i * 64 + lane];
    float a1 = selfw * h[(size_t)i * 64 + 32 + lane];
    int beg = d_rowptr[i];
    int end = d_rowptr[i + 1];
    int j = beg;
    for (; j + 2 <= end; j += 2) {
        int s0 = d_csr_src[j], s1 = d_csr_src[j + 1];
        float w0 = d_csr_w[j], w1 = d_csr_w[j + 1];
        float v00 = h[(size_t)s0 * 64 + lane];
        float v01 = h[(size_t)s0 * 64 + 32 + lane];
        float v10 = h[(size_t)s1 * 64 + lane];
        float v11 = h[(size_t)s1 * 64 + 32 + lane];
        a0 += w0 * v00 + w1 * v10;
        a1 += w0 * v01 + w1 * v11;
    }
    if (j < end) {
        int s = d_csr_src[j];
        float w = d_csr_w[j];
        a0 += w * h[(size_t)s * 64 + lane];
        a1 += w * h[(size_t)s * 64 + 32 + lane];
    }
    a0 = fmaxf(a0 + bias[lane], 0.0f);
    a1 = fmaxf(a1 + bias[32 + lane], 0.0f);
    float zi = a0 * d_vg[lane] + a1 * d_vg[32 + lane];
#pragma unroll
    for (int off = 16; off > 0; off >>= 1)
        zi += __shfl_down_sync(0xFFFFFFFFu, zi, off);
    if (lane == 0) z[i] = zi;
}

// ---------------- scalar aggregation 2 + final combine ----------------
__global__ void gcn_agg2_out(const float* __restrict__ z, const float* __restrict__ smlp,
                             float* __restrict__ out) {
    int gw = (blockIdx.x * blockDim.x + threadIdx.x) >> 5;
    int lane = threadIdx.x & 31;
    if (gw >= NN) return;
    int i = gw;
    float di = d_dinv[i];
    float acc = (lane == 0) ? di * di * z[i] : 0.0f;
    int beg = d_rowptr[i];
    int end = d_rowptr[i + 1];
    for (int j = beg + lane; j < end; j += 32)
        acc += d_csr_w[j] * z[d_csr_src[j]];
#pragma unroll
    for (int off = 16; off > 0; off >>= 1)
        acc += __shfl_down_sync(0xFFFFFFFFu, acc, off);
    if (lane == 0) out[i] = acc + smlp[i] + d_cmlp + d_cgnn;
}

// ---------------- tf32 helpers ----------------
__device__ __forceinline__ uint32_t f2tf32(float f) {
    uint32_t u;
    asm("cvt.rna.tf32.f32 %0, %1;" : "=r"(u) : "f"(f));
    return u;
}

__device__ __forceinline__ void mma_tf32(float c[4], uint4 a, uint2 b) {
    asm volatile(
        "mma.sync.aligned.m16n8k8.row.col.f32.tf32.tf32.f32 "
        "{%0,%1,%2,%3},{%4,%5,%6,%7},{%8,%9},{%0,%1,%2,%3};\n"
        : "+f"(c[0]), "+f"(c[1]), "+f"(c[2]), "+f"(c[3])
        : "r"(a.x), "r"(a.y), "r"(a.z), "r"(a.w), "r"(b.x), "r"(b.y));
}

// fragment-store helpers (A 128x32 tile, paired-B 32x64 tile)
__device__ __forceinline__ void stsA_frag(uint32_t* buf, const float4* av, int tid) {
#pragma unroll
    for (int i = 0; i < 4; i++) {
        int idx = tid + i * 256;
        int r = idx >> 3;
        int cv = (idx & 7) << 2;
        int slab = r >> 5, mtile = (r >> 4) & 1, rr = r & 15;
        int kstep = cv >> 3, ccb = cv & 7;
        int reg = (rr >> 3) + ((ccb >> 2) << 1);
        int lane0 = (rr & 7) << 2;
        uint32_t o = ((((slab * 2 + mtile) * 4 + kstep) * 32 + lane0) << 2) + reg;
        buf[o + 0]  = f2tf32(av[i].x);
        buf[o + 4]  = f2tf32(av[i].y);
        buf[o + 8]  = f2tf32(av[i].z);
        buf[o + 12] = f2tf32(av[i].w);
    }
}

__device__ __forceinline__ void stsB_frag(uint32_t* buf, const float4* bv, int tid) {
#pragma unroll
    for (int i = 0; i < 2; i++) {
        int idx = tid + i * 256;
        int r = idx >> 4;
        int cv = (idx & 15) << 2;
        int kstep = r >> 3, kk = r & 7;
        int reg = kk >> 2;
        int nslab = cv >> 5, ntile = (cv >> 3) & 3;
        int ntpair = ntile >> 1, ntodd = ntile & 1;
        int lane0 = 4 * (cv & 7) + (kk & 3);
        uint32_t o = (((((nslab * 2 + ntpair) * 4) + kstep) * 32 + lane0) << 2) + ntodd * 2 + reg;
        buf[o + 0]  = f2tf32(bv[i].x);
        buf[o + 16] = f2tf32(bv[i].y);
        buf[o + 32] = f2tf32(bv[i].z);
        buf[o + 48] = f2tf32(bv[i].w);
    }
}

// ---------------- standalone tf32 GEMM (gcn1 transform: h1 = x @ g1W) ----------------
__global__ __launch_bounds__(256) void tf32_gemm(
    int M, int N, int K,
    const float* __restrict__ A, const float* __restrict__ B,
    float* __restrict__ C) {

    __shared__ uint32_t sA[4096];
    __shared__ uint32_t sB[2048];

    const int tid = threadIdx.x;
    const int brow = blockIdx.y;
    const int bcol = blockIdx.x;
    const int w = tid >> 5;
    const int lane = tid & 31;
    const int wm = w & 3;
    const int wn = w >> 2;

    float acc[2][4][4] = {};

    for (int k0 = 0; k0 < K; k0 += 32) {
        float4 av[4], bv[2];
#pragma unroll
        for (int i = 0; i < 4; i++) {
            int idx = tid + i * 256;
            int r = idx >> 3;
            int cv = (idx & 7) << 2;
            int grow = brow * 128 + r;
            av[i] = make_float4(0.f, 0.f, 0.f, 0.f);
            if (grow < M) av[i] = *(const float4*)&A[(size_t)grow * K + k0 + cv];
        }
#pragma unroll
        for (int i = 0; i < 2; i++) {
            int idx = tid + i * 256;
            int r = idx >> 4;
            int cv = (idx & 15) << 2;
            bv[i] = *(const float4*)&B[(size_t)(k0 + r) * N + bcol * 64 + cv];
        }
        stsA_frag(sA, av, tid);
        stsB_frag(sB, bv, tid);
        __syncthreads();

#pragma unroll
        for (int ks = 0; ks < 4; ks++) {
            uint4 a0 = *(const uint4*)&sA[(((wm * 2 + 0) * 4 + ks) * 32 + lane) << 2];
            uint4 a1 = *(const uint4*)&sA[(((wm * 2 + 1) * 4 + ks) * 32 + lane) << 2];
            uint4 bb0 = *(const uint4*)&sB[((((wn * 2 + 0) * 4) + ks) * 32 + lane) << 2];
            uint4 bb1 = *(const uint4*)&sB[((((wn * 2 + 1) * 4) + ks) * 32 + lane) << 2];
            uint2 b[4];
            b[0] = make_uint2(bb0.x, bb0.y);
            b[1] = make_uint2(bb0.z, bb0.w);
            b[2] = make_uint2(bb1.x, bb1.y);
            b[3] = make_uint2(bb1.z, bb1.w);
#pragma unroll
            for (int nt = 0; nt < 4; nt++) {
                mma_tf32(acc[0][nt], a0, b[nt]);
                mma_tf32(acc[1][nt], a1, b[nt]);
            }
        }
        __syncthreads();
    }

    const int g = lane >> 2;
    const int t4 = lane & 3;
#pragma unroll
    for (int mt = 0; mt < 2; mt++) {
#pragma unroll
        for (int nt = 0; nt < 4; nt++) {
            int gcol = bcol * 64 + wn * 32 + nt * 8 + t4 * 2;
            int grow0 = brow * 128 + wm * 32 + mt * 16 + g;
            if (grow0 < M)
                *(float2*)&C[(size_t)grow0 * N + gcol] = make_float2(acc[mt][nt][0], acc[mt][nt][1]);
            if (grow0 + 8 < M)
                *(float2*)&C[(size_t)(grow0 + 8) * N + gcol] = make_float2(acc[mt][nt][2], acc[mt][nt][3]);
        }
    }
}

// ---------------- MLP GEMM with collapsed epilogue ----------------
// s_mlp[row] += sum_cols relu(uf@W1 + b1)[row, col] * w2f[col]   (per 64-col chunk)
// BM=128, BN=64, BK=32, double-buffered, 2 CTAs/SM.
// smem words: sA 2x4096 | sB 2x2048 | sRed 128  = 12416 words = 49664 B
#define MG_SMEM_BYTES (12416 * 4)

__global__ __launch_bounds__(256, 2) void mlp_gemm(
    int M, const float* __restrict__ A, const float* __restrict__ W1,
    const float* __restrict__ b1, float* __restrict__ s_mlp) {

    extern __shared__ uint32_t sm[];
    uint32_t* sA = sm;           // 2 x 4096
    uint32_t* sB = sm + 8192;    // 2 x 2048
    float*    sRed = (float*)(sm + 12288);

    const int tid = threadIdx.x;
    const int brow = blockIdx.y;
    const int bcol = blockIdx.x;
    const int w = tid >> 5;
    const int lane = tid & 31;
    const int wm = w & 3;
    const int wn = w >> 2;
    const int g = lane >> 2;
    const int t4 = lane & 3;

    if (tid < 128) sRed[tid] = 0.0f;

    float acc[2][4][4] = {};

    // prologue: load + stage kt=0
    float4 av[4], bv[2];
#pragma unroll
    for (int i = 0; i < 4; i++) {
        int idx = tid + i * 256;
        int r = idx >> 3;
        int cv = (idx & 7) << 2;
        int grow = brow * 128 + r;
        av[i] = make_float4(0.f, 0.f, 0.f, 0.f);
        if (grow < M) av[i] = *(const float4*)&A[(size_t)grow * 256 + cv];
    }
#pragma unroll
    for (int i = 0; i < 2; i++) {
        int idx = tid + i * 256;
        int r = idx >> 4;
        int cv = (idx & 15) << 2;
        bv[i] = *(const float4*)&W1[(size_t)r * 512 + bcol * 64 + cv];
    }
    stsA_frag(sA, av, tid);
    stsB_frag(sB, bv, tid);
    __syncthreads();

#pragma unroll
    for (int kt = 0; kt < 8; kt++) {
        float4 nav[4], nbv[2];
        if (kt < 7) {
#pragma unroll
            for (int i = 0; i < 4; i++) {
                int idx = tid + i * 256;
                int r = idx >> 3;
                int cv = (idx & 7) << 2;
                int grow = brow * 128 + r;
                nav[i] = make_float4(0.f, 0.f, 0.f, 0.f);
                if (grow < M) nav[i] = *(const float4*)&A[(size_t)grow * 256 + (kt + 1) * 32 + cv];
            }
#pragma unroll
            for (int i = 0; i < 2; i++) {
                int idx = tid + i * 256;
                int r = idx >> 4;
                int cv = (idx & 15) << 2;
                nbv[i] = *(const float4*)&W1[(size_t)((kt + 1) * 32 + r) * 512 + bcol * 64 + cv];
            }
        }
        uint32_t* bufA = sA + (kt & 1) * 4096;
        uint32_t* bufB = sB + (kt & 1) * 2048;
#pragma unroll
        for (int ks = 0; ks < 4; ks++) {
            uint4 a0 = *(const uint4*)&bufA[(((wm * 2 + 0) * 4 + ks) * 32 + lane) << 2];
            uint4 a1 = *(const uint4*)&bufA[(((wm * 2 + 1) * 4 + ks) * 32 + lane) << 2];
            uint4 bb0 = *(const uint4*)&bufB[((((wn * 2 + 0) * 4) + ks) * 32 + lane) << 2];
            uint4 bb1 = *(const uint4*)&bufB[((((wn * 2 + 1) * 4) + ks) * 32 + lane) << 2];
            uint2 b[4];
            b[0] = make_uint2(bb0.x, bb0.y);
            b[1] = make_uint2(bb0.z, bb0.w);
            b[2] = make_uint2(bb1.x, bb1.y);
            b[3] = make_uint2(bb1.z, bb1.w);
#pragma unroll
            for (int nt = 0; nt < 4; nt++) {
                mma_tf32(acc[0][nt], a0, b[nt]);
                mma_tf32(acc[1][nt], a1, b[nt]);
            }
        }
        if (kt < 7) {
            stsA_frag(sA + ((kt + 1) & 1) * 4096, nav, tid);
            stsB_frag(sB + ((kt + 1) & 1) * 2048, nbv, tid);
            __syncthreads();
        }
    }

    // ---- epilogue: relu + dot with w2f, reduce to per-row partials ----
    float p[2][2] = {{0.f, 0.f}, {0.f, 0.f}};
#pragma unroll
    for (int nt = 0; nt < 4; nt++) {
        int gcol = bcol * 64 + wn * 32 + nt * 8 + t4 * 2;
        float bb0 = b1[gcol], bb1 = b1[gcol + 1];
        float w0 = d_w2f[gcol], w1 = d_w2f[gcol + 1];
#pragma unroll
        for (int mt = 0; mt < 2; mt++) {
            p[mt][0] += fmaxf(acc[mt][nt][0] + bb0, 0.f) * w0 + fmaxf(acc[mt][nt][1] + bb1, 0.f) * w1;
            p[mt][1] += fmaxf(acc[mt][nt][2] + bb0, 0.f) * w0 + fmaxf(acc[mt][nt][3] + bb1, 0.f) * w1;
        }
    }
#pragma unroll
    for (int off = 1; off <= 2; off <<= 1) {
        p[0][0] += __shfl_xor_sync(0xFFFFFFFFu, p[0][0], off);
        p[0][1] += __shfl_xor_sync(0xFFFFFFFFu, p[0][1], off);
        p[1][0] += __shfl_xor_sync(0xFFFFFFFFu, p[1][0], off);
        p[1][1] += __shfl_xor_sync(0xFFFFFFFFu, p[1][1], off);
    }
    __syncthreads();   // sRed init + mma complete on all warps
    if (t4 == 0) {
        atomicAdd(&sRed[wm * 32 + g],          p[0][0]);
        atomicAdd(&sRed[wm * 32 + g + 8],      p[0][1]);
        atomicAdd(&sRed[wm * 32 + 16 + g],     p[1][0]);
        atomicAdd(&sRed[wm * 32 + 16 + g + 8], p[1][1]);
    }
    __syncthreads();
    if (tid < 128) {
        int grow = brow * 128 + tid;
        if (grow < M) atomicAdd(&s_mlp[grow], sRed[tid]);
    }
}

// ---------------- launch ----------------
extern "C" void kernel_launch(void* const* d_in, const int* in_sizes, int n_in,
                              void* d_out, int out_size) {
    const float* x     = (const float*)d_in[0];
    const int*   ei    = (const int*)d_in[1];
    const float* ea    = (const float*)d_in[2];
    const float* uf    = (const float*)d_in[3];
    const float* g1W   = (const float*)d_in[4];
    const float* g1b   = (const float*)d_in[5];
    const float* g2W   = (const float*)d_in[6];
    const float* g2b   = (const float*)d_in[7];
    const float* fc1W  = (const float*)d_in[8];
    const float* fc1b  = (const float*)d_in[9];
    const float* fc2W  = (const float*)d_in[10];
    const float* fc2b  = (const float*)d_in[11];
    const float* fcfW  = (const float*)d_in[12];
    const float* fcfb  = (const float*)d_in[13];
    float* out = (float*)d_out;

    const int* src = ei;
    const int* dst = ei + NE;

    void* p;
    cudaGetSymbolAddress(&p, d_h1);   float* h1   = (float*)p;
    cudaGetSymbolAddress(&p, d_z);    float* z    = (float*)p;
    cudaGetSymbolAddress(&p, d_smlp); float* smlp = (float*)p;

    const int NB_NODE = (NN + 255) / 256;
    const int NB_EDGE = (NE + 255) / 256;
    const int NB_WARP = (NN * 32 + 255) / 256;
    const int MB = (NN + 127) / 128;   // 391

    static cudaStream_t sMlp = nullptr, sGnn = nullptr;
    static cudaEvent_t evFork = nullptr, evMlp = nullptr, evGemm1 = nullptr, evPrep = nullptr;
    static bool inited = false;
    if (!inited) {
        cudaStreamCreateWithFlags(&sMlp, cudaStreamNonBlocking);
        cudaStreamCreateWithFlags(&sGnn, cudaStreamNonBlocking);
        cudaEventCreateWithFlags(&evFork, cudaEventDisableTiming);
        cudaEventCreateWithFlags(&evMlp, cudaEventDisableTiming);
        cudaEventCreateWithFlags(&evGemm1, cudaEventDisableTiming);
        cudaEventCreateWithFlags(&evPrep, cudaEventDisableTiming);
        cudaFuncSetAttribute(mlp_gemm, cudaFuncAttributeMaxDynamicSharedMemorySize,
                             MG_SMEM_BYTES);
        inited = true;
    }

    cudaEventRecord(evFork, 0);
    cudaStreamWaitEvent(sGnn, evFork, 0);
    cudaStreamWaitEvent(sMlp, evFork, 0);

    // sMlp: precompute vectors, zero accumulator, run collapsed MLP GEMM
    prep_vecs<<<1, 512, 0, sMlp>>>(fc2W, g2W, fc2b, g2b, fcfW, fcfb);
    cudaEventRecord(evPrep, sMlp);
    zero_smlp<<<NB_NODE, 256, 0, sMlp>>>();
    mlp_gemm<<<dim3(8, MB), 256, MG_SMEM_BYTES, sMlp>>>(NN, uf, fc1W, fc1b, smlp);
    cudaEventRecord(evMlp, sMlp);

    // sGnn: node-feature transform (independent of graph preprocessing)
    tf32_gemm<<<dim3(1, MB), 256, 0, sGnn>>>(NN, 64, 256, x, g1W, h1);
    cudaEventRecord(evGemm1, sGnn);

    // main stream: graph preprocessing
    init_nodes<<<NB_NODE, 256>>>();
    edge_deg_count<<<NB_EDGE, 256>>>(src, dst, ea);
    compute_dinv<<<NB_NODE, 256>>>();
    scan_block<<<SCAN_B, SCAN_T>>>();
    scan_top<<<1, 64>>>();
    finalize_rowptr<<<NB_NODE, 256>>>();
    fill_csr<<<NB_EDGE, 256>>>(src, dst, ea);

    // aggregation 1 (+relu, + z-dot); needs h1 and d_vg
    cudaStreamWaitEvent(0, evGemm1, 0);
    cudaStreamWaitEvent(0, evPrep, 0);
    gcn_agg1_z<<<NB_WARP, 256>>>(h1, g1b, z);

    // scalar aggregation 2 + final combine; needs s_mlp
    cudaStreamWaitEvent(0, evMlp, 0);
    gcn_agg2_out<<<NB_WARP, 256>>>(z, smlp, out);
}

// round 7
// speedup vs baseline: 1.7443x; 1.7443x over previous
#include <cuda_runtime.h>
#include <cstdint>
#include <cstddef>

#define NN 50000
#define NE 800000
#define SCAN_T 1024
#define SCAN_B ((NN + SCAN_T - 1) / SCAN_T)   // 49

// ---------------- static device scratch ----------------
__device__ float d_deg[NN];
__device__ float d_dinv[NN];
__device__ int   d_counts[NN];
__device__ int   d_scanned[NN];
__device__ int   d_scanblk[SCAN_B];
__device__ int   d_rowptr[NN + 1];
__device__ int   d_wp[NN];
__device__ int   d_csr_src[NE];
__device__ float d_csr_w[NE];
__device__ float d_h1[NN * 64];
__device__ float d_z[NN];
__device__ float d_smlp[NN];
__device__ float d_w2f[512];   // fc2_W @ fcf_W[0:64]
__device__ float d_vg[64];     // gcn2_W @ fcf_W[64:128]
__device__ float d_cmlp;       // fc2_b . fcf_W[0:64]
__device__ float d_cgnn;       // gcn2_b . fcf_W[64:128] + fcf_b

// ---------------- precompute collapsed vectors ----------------
__global__ void prep_vecs(const float* __restrict__ W2, const float* __restrict__ g2W,
                          const float* __restrict__ b2, const float* __restrict__ g2b,
                          const float* __restrict__ Wf, const float* __restrict__ fb) {
    int t = threadIdx.x;   // 512 threads
    float s = 0.f;
#pragma unroll 8
    for (int c = 0; c < 64; c++) s += W2[t * 64 + c] * Wf[c];
    d_w2f[t] = s;
    if (t < 64) {
        float s2 = 0.f;
#pragma unroll 8
        for (int c = 0; c < 64; c++) s2 += g2W[t * 64 + c] * Wf[64 + c];
        d_vg[t] = s2;
    }
    if (t == 0) {
        float cm = 0.f, cg = 0.f;
        for (int c = 0; c < 64; c++) { cm += b2[c] * Wf[c]; cg += g2b[c] * Wf[64 + c]; }
        d_cmlp = cm;
        d_cgnn = cg + fb[0];
    }
}

// ---------------- graph preprocessing ----------------
__global__ void init_nodes() {
    int i = blockIdx.x * blockDim.x + threadIdx.x;
    if (i < NN) { d_deg[i] = 1.0f; d_counts[i] = 0; }
}

__global__ void edge_deg_count(const int* __restrict__ src, const int* __restrict__ dst,
                               const float* __restrict__ ew) {
    int e = blockIdx.x * blockDim.x + threadIdx.x;
    if (e < NE) {
        int d = dst[e];
        atomicAdd(&d_deg[d], ew[e]);
        atomicAdd(&d_counts[d], 1);
    }
}

__global__ void compute_dinv() {
    int i = blockIdx.x * blockDim.x + threadIdx.x;
    if (i < NN) {
        float dg = d_deg[i];
        d_dinv[i] = (dg > 0.0f) ? rsqrtf(fmaxf(dg, 1e-12f)) : 0.0f;
    }
}

__global__ void scan_block() {
    __shared__ int s[SCAN_T];
    int tid = threadIdx.x;
    int i = blockIdx.x * SCAN_T + tid;
    int v = (i < NN) ? d_counts[i] : 0;
    s[tid] = v;
    __syncthreads();
#pragma unroll
    for (int off = 1; off < SCAN_T; off <<= 1) {
        int t = (tid >= off) ? s[tid - off] : 0;
        __syncthreads();
        s[tid] += t;
        __syncthreads();
    }
    if (i < NN) d_scanned[i] = s[tid];
    if (tid == SCAN_T - 1) d_scanblk[blockIdx.x] = s[tid];
}

__global__ void scan_top() {
    __shared__ int s[64];
    int tid = threadIdx.x;
    int v = (tid < SCAN_B) ? d_scanblk[tid] : 0;
    s[tid] = v;
    __syncthreads();
#pragma unroll
    for (int off = 1; off < 64; off <<= 1) {
        int t = (tid >= off) ? s[tid - off] : 0;
        __syncthreads();
        s[tid] += t;
        __syncthreads();
    }
    if (tid < SCAN_B) d_scanblk[tid] = (tid == 0) ? 0 : s[tid - 1];
}

__global__ void finalize_rowptr() {
    int i = blockIdx.x * blockDim.x + threadIdx.x;
    if (i < NN) {
        int incl = d_scanned[i] + d_scanblk[i >> 10];
        d_rowptr[i + 1] = incl;
        int excl = (i == 0) ? 0 : (d_scanned[i - 1] + d_scanblk[(i - 1) >> 10]);
        d_wp[i] = excl;
        if (i == 0) d_rowptr[0] = 0;
    }
}

__global__ void fill_csr(const int* __restrict__ src, const int* __restrict__ dst,
                         const float* __restrict__ ew) {
    int e = blockIdx.x * blockDim.x + threadIdx.x;
    if (e < NE) {
        int s = src[e];
        int d = dst[e];
        int pos = atomicAdd(&d_wp[d], 1);
        d_csr_src[pos] = s;
        d_csr_w[pos] = d_dinv[s] * ew[e] * d_dinv[d];
    }
}

// ---------------- GCN aggregation 1 + relu + z = g . vg ----------------
__global__ void gcn_agg1_z(const float* __restrict__ h, const float* __restrict__ bias,
                           float* __restrict__ z) {
    int gw = (blockIdx.x * blockDim.x + threadIdx.x) >> 5;
    int lane = threadIdx.x & 31;
    if (gw >= NN) return;
    int i = gw;
    float di = d_dinv[i];
    float selfw = di * di;
    float a0 = selfw * h[(size_t)i * 64 + lane];
    float a1 = selfw * h[(size_t)i * 64 + 32 + lane];
    int beg = d_rowptr[i];
    int end = d_rowptr[i + 1];
    int j = beg;
    for (; j + 2 <= end; j += 2) {
        int s0 = d_csr_src[j], s1 = d_csr_src[j + 1];
        float w0 = d_csr_w[j], w1 = d_csr_w[j + 1];
        float v00 = h[(size_t)s0 * 64 + lane];
        float v01 = h[(size_t)s0 * 64 + 32 + lane];
        float v10 = h[(size_t)s1 * 64 + lane];
        float v11 = h[(size_t)s1 * 64 + 32 + lane];
        a0 += w0 * v00 + w1 * v10;
        a1 += w0 * v01 + w1 * v11;
    }
    if (j < end) {
        int s = d_csr_src[j];
        float w = d_csr_w[j];
        a0 += w * h[(size_t)s * 64 + lane];
        a1 += w * h[(size_t)s * 64 + 32 + lane];
    }
    a0 = fmaxf(a0 + bias[lane], 0.0f);
    a1 = fmaxf(a1 + bias[32 + lane], 0.0f);
    float zi = a0 * d_vg[lane] + a1 * d_vg[32 + lane];
#pragma unroll
    for (int off = 16; off > 0; off >>= 1)
        zi += __shfl_down_sync(0xFFFFFFFFu, zi, off);
    if (lane == 0) z[i] = zi;
}

// ---------------- scalar aggregation 2 + final combine ----------------
__global__ void gcn_agg2_out(const float* __restrict__ z, const float* __restrict__ smlp,
                             float* __restrict__ out) {
    int gw = (blockIdx.x * blockDim.x + threadIdx.x) >> 5;
    int lane = threadIdx.x & 31;
    if (gw >= NN) return;
    int i = gw;
    float di = d_dinv[i];
    float acc = (lane == 0) ? di * di * z[i] : 0.0f;
    int beg = d_rowptr[i];
    int end = d_rowptr[i + 1];
    for (int j = beg + lane; j < end; j += 32)
        acc += d_csr_w[j] * z[d_csr_src[j]];
#pragma unroll
    for (int off = 16; off > 0; off >>= 1)
        acc += __shfl_down_sync(0xFFFFFFFFu, acc, off);
    if (lane == 0) out[i] = acc + smlp[i] + d_cmlp + d_cgnn;
}

// ---------------- tf32 / cp.async helpers ----------------
__device__ __forceinline__ uint32_t f2tf32(float f) {
    uint32_t u;
    asm("cvt.rna.tf32.f32 %0, %1;" : "=r"(u) : "f"(f));
    return u;
}

__device__ __forceinline__ void mma_tf32(float c[4], uint4 a, uint2 b) {
    asm volatile(
        "mma.sync.aligned.m16n8k8.row.col.f32.tf32.tf32.f32 "
        "{%0,%1,%2,%3},{%4,%5,%6,%7},{%8,%9},{%0,%1,%2,%3};\n"
        : "+f"(c[0]), "+f"(c[1]), "+f"(c[2]), "+f"(c[3])
        : "r"(a.x), "r"(a.y), "r"(a.z), "r"(a.w), "r"(b.x), "r"(b.y));
}

__device__ __forceinline__ uint32_t smem_u32(const void* p) {
    return (uint32_t)__cvta_generic_to_shared(p);
}
__device__ __forceinline__ void cp16(uint32_t dst, const void* src) {
    asm volatile("cp.async.cg.shared.global [%0], [%1], 16;" :: "r"(dst), "l"(src));
}
#define CP_COMMIT() asm volatile("cp.async.commit_group;" ::: "memory")
#define CP_WAIT(n)  asm volatile("cp.async.wait_group %0;" :: "n"(n) : "memory")

// Smem layouts (row-major + XOR swizzle, all fragment loads bank-conflict-free):
//   A tile 128x32: word = row*32 + (k ^ ((row&7)<<2))
//   B tile 32xBN : word = k*BN  + (n ^ ((k&3)<<3))

// ---------------- MLP GEMM: s_mlp[row] += relu(uf@W1+b1)[row,:] . w2f ----------------
// BM=128, BN=128, BK=32, 3-stage cp.async, grid (4, 391), 256 thr (4wm x 2wn, warp 32x64)
#define MLP_SMEM_BYTES ((3 * 4096 + 3 * 4096 + 128) * 4)

__global__ __launch_bounds__(256, 2) void mlp_gemm(
    int M, const float* __restrict__ A, const float* __restrict__ W1,
    const float* __restrict__ b1, float* __restrict__ s_mlp) {

    extern __shared__ float sm[];
    float* sA = sm;                // 3 x 4096
    float* sB = sm + 3 * 4096;     // 3 x 4096
    float* sRed = sm + 6 * 4096;   // 128

    const int tid = threadIdx.x, brow = blockIdx.y, bcol = blockIdx.x;
    const int w = tid >> 5, lane = tid & 31, wm = w & 3, wn = w >> 5 ? 0 : (w >> 2);
    const int g = lane >> 2, t = lane & 3;
    const int swA = g << 2;
    if (tid < 128) sRed[tid] = 0.f;

    const uint32_t sAu = smem_u32(sA), sBu = smem_u32(sB);

    // cp.async one k-tile into stage s
    auto issue = [&](int kt, int s) {
#pragma unroll
        for (int i = 0; i < 4; i++) {
            int idx = tid + i * 256;
            int row = idx >> 3, c = idx & 7;
            int grow = brow * 128 + row; if (grow >= M) grow = M - 1;
            uint32_t dst = sAu + (uint32_t)(s * 4096 + row * 32 + ((c ^ (row & 7)) << 2)) * 4u;
            cp16(dst, &A[(size_t)grow * 256 + kt * 32 + c * 4]);
        }
#pragma unroll
        for (int i = 0; i < 4; i++) {
            int idx = tid + i * 256;
            int k = idx >> 5, c = idx & 31;
            uint32_t dst = sBu + (uint32_t)(s * 4096 + k * 128 + ((c ^ ((k & 3) << 1)) << 2)) * 4u;
            cp16(dst, &W1[(size_t)(kt * 32 + k) * 512 + bcol * 128 + c * 4]);
        }
        CP_COMMIT();
    };

    float acc[2][8][4] = {};

    issue(0, 0);
    issue(1, 1);
#pragma unroll
    for (int kt = 0; kt < 8; kt++) {
        if (kt == 7) { CP_WAIT(0); } else { CP_WAIT(1); }
        __syncthreads();
        const float* bA = sA + (kt % 3) * 4096;
        const float* bB = sB + (kt % 3) * 4096;
#pragma unroll
        for (int ks = 0; ks < 4; ks++) {
            const int kb = ks * 8;
            uint4 a[2];
#pragma unroll
            for (int mt = 0; mt < 2; mt++) {
                int r0 = wm * 32 + mt * 16 + g;
                int r1 = r0 + 8;
                a[mt].x = f2tf32(bA[r0 * 32 + ((kb + t) ^ swA)]);
                a[mt].y = f2tf32(bA[r1 * 32 + ((kb + t) ^ swA)]);
                a[mt].z = f2tf32(bA[r0 * 32 + ((kb + t + 4) ^ swA)]);
                a[mt].w = f2tf32(bA[r1 * 32 + ((kb + t + 4) ^ swA)]);
            }
#pragma unroll
            for (int nt = 0; nt < 8; nt++) {
                int n = wn * 64 + nt * 8 + g;
                uint2 b;
                b.x = f2tf32(bB[(kb + t) * 128 + (n ^ (t << 3))]);
                b.y = f2tf32(bB[(kb + t + 4) * 128 + (n ^ (t << 3))]);
                mma_tf32(acc[0][nt], a[0], b);
                mma_tf32(acc[1][nt], a[1], b);
            }
        }
        if (kt < 6) issue(kt + 2, (kt + 2) % 3);
    }

    // epilogue: relu + dot with w2f
    float p[2][2] = {{0.f, 0.f}, {0.f, 0.f}};
#pragma unroll
    for (int nt = 0; nt < 8; nt++) {
        int gcol = bcol * 128 + wn * 64 + nt * 8 + t * 2;
        float bb0 = b1[gcol], bb1 = b1[gcol + 1];
        float w0 = d_w2f[gcol], w1 = d_w2f[gcol + 1];
#pragma unroll
        for (int mt = 0; mt < 2; mt++) {
            p[mt][0] += fmaxf(acc[mt][nt][0] + bb0, 0.f) * w0 + fmaxf(acc[mt][nt][1] + bb1, 0.f) * w1;
            p[mt][1] += fmaxf(acc[mt][nt][2] + bb0, 0.f) * w0 + fmaxf(acc[mt][nt][3] + bb1, 0.f) * w1;
        }
    }
#pragma unroll
    for (int off = 1; off <= 2; off <<= 1) {
        p[0][0] += __shfl_xor_sync(0xFFFFFFFFu, p[0][0], off);
        p[0][1] += __shfl_xor_sync(0xFFFFFFFFu, p[0][1], off);
        p[1][0] += __shfl_xor_sync(0xFFFFFFFFu, p[1][0], off);
        p[1][1] += __shfl_xor_sync(0xFFFFFFFFu, p[1][1], off);
    }
    if (t == 0) {
#pragma unroll
        for (int mt = 0; mt < 2; mt++) {
            int r0 = wm * 32 + mt * 16 + g;
            atomicAdd(&sRed[r0], p[mt][0]);
            atomicAdd(&sRed[r0 + 8], p[mt][1]);
        }
    }
    __syncthreads();
    if (tid < 128) {
        int grow = brow * 128 + tid;
        if (grow < M) atomicAdd(&s_mlp[grow], sRed[tid]);
    }
}

// ---------------- GCN1 transform: h1 = x @ g1W (M=NN, N=64, K=256) ----------------
// BM=128, BN=64, BK=32, 3-stage cp.async, grid (391), 256 thr (4wm x 2wn, warp 32x32)
#define G1_SMEM_BYTES ((3 * 4096 + 3 * 2048) * 4)

__global__ __launch_bounds__(256, 2) void gcn1_gemm(
    int M, const float* __restrict__ A, const float* __restrict__ B,
    float* __restrict__ C) {

    extern __shared__ float sm[];
    float* sA = sm;                // 3 x 4096
    float* sB = sm + 3 * 4096;     // 3 x 2048

    const int tid = threadIdx.x, brow = blockIdx.x;
    const int w = tid >> 5, lane = tid & 31, wm = w & 3, wn = w >> 2;
    const int g = lane >> 2, t = lane & 3;
    const int swA = g << 2;

    const uint32_t sAu = smem_u32(sA), sBu = smem_u32(sB);

    auto issue = [&](int kt, int s) {
#pragma unroll
        for (int i = 0; i < 4; i++) {
            int idx = tid + i * 256;
            int row = idx >> 3, c = idx & 7;
            int grow = brow * 128 + row; if (grow >= M) grow = M - 1;
            uint32_t dst = sAu + (uint32_t)(s * 4096 + row * 32 + ((c ^ (row & 7)) << 2)) * 4u;
            cp16(dst, &A[(size_t)grow * 256 + kt * 32 + c * 4]);
        }
#pragma unroll
        for (int i = 0; i < 2; i++) {
            int idx = tid + i * 256;
            int k = idx >> 4, c = idx & 15;
            uint32_t dst = sBu + (uint32_t)(s * 2048 + k * 64 + ((c ^ ((k & 3) << 1)) << 2)) * 4u;
            cp16(dst, &B[(size_t)(kt * 32 + k) * 64 + c * 4]);
        }
        CP_COMMIT();
    };

    float acc[2][4][4] = {};

    issue(0, 0);
    issue(1, 1);
#pragma unroll
    for (int kt = 0; kt < 8; kt++) {
        if (kt == 7) { CP_WAIT(0); } else { CP_WAIT(1); }
        __syncthreads();
        const float* bA = sA + (kt % 3) * 4096;
        const float* bB = sB + (kt % 3) * 2048;
#pragma unroll
        for (int ks = 0; ks < 4; ks++) {
            const int kb = ks * 8;
            uint4 a[2];
#pragma unroll
            for (int mt = 0; mt < 2; mt++) {
                int r0 = wm * 32 + mt * 16 + g;
                int r1 = r0 + 8;
                a[mt].x = f2tf32(bA[r0 * 32 + ((kb + t) ^ swA)]);
                a[mt].y = f2tf32(bA[r1 * 32 + ((kb + t) ^ swA)]);
                a[mt].z = f2tf32(bA[r0 * 32 + ((kb + t + 4) ^ swA)]);
                a[mt].w = f2tf32(bA[r1 * 32 + ((kb + t + 4) ^ swA)]);
            }
#pragma unroll
            for (int nt = 0; nt < 4; nt++) {
                int n = wn * 32 + nt * 8 + g;
                uint2 b;
                b.x = f2tf32(bB[(kb + t) * 64 + (n ^ (t << 3))]);
                b.y = f2tf32(bB[(kb + t + 4) * 64 + (n ^ (t << 3))]);
                mma_tf32(acc[0][nt], a[0], b);
                mma_tf32(acc[1][nt], a[1], b);
            }
        }
        if (kt < 6) issue(kt + 2, (kt + 2) % 3);
    }

#pragma unroll
    for (int mt = 0; mt < 2; mt++) {
#pragma unroll
        for (int nt = 0; nt < 4; nt++) {
            int gcol = wn * 32 + nt * 8 + t * 2;
            int grow0 = brow * 128 + wm * 32 + mt * 16 + g;
            if (grow0 < M)
                *(float2*)&C[(size_t)grow0 * 64 + gcol] = make_float2(acc[mt][nt][0], acc[mt][nt][1]);
            if (grow0 + 8 < M)
                *(float2*)&C[(size_t)(grow0 + 8) * 64 + gcol] = make_float2(acc[mt][nt][2], acc[mt][nt][3]);
        }
    }
}

// ---------------- launch ----------------
extern "C" void kernel_launch(void* const* d_in, const int* in_sizes, int n_in,
                              void* d_out, int out_size) {
    const float* x     = (const float*)d_in[0];
    const int*   ei    = (const int*)d_in[1];
    const float* ea    = (const float*)d_in[2];
    const float* uf    = (const float*)d_in[3];
    const float* g1W   = (const float*)d_in[4];
    const float* g1b   = (const float*)d_in[5];
    const float* g2W   = (const float*)d_in[6];
    const float* g2b   = (const float*)d_in[7];
    const float* fc1W  = (const float*)d_in[8];
    const float* fc1b  = (const float*)d_in[9];
    const float* fc2W  = (const float*)d_in[10];
    const float* fc2b  = (const float*)d_in[11];
    const float* fcfW  = (const float*)d_in[12];
    const float* fcfb  = (const float*)d_in[13];
    float* out = (float*)d_out;

    const int* src = ei;
    const int* dst = ei + NE;

    void* p;
    cudaGetSymbolAddress(&p, d_h1);   float* h1   = (float*)p;
    cudaGetSymbolAddress(&p, d_z);    float* z    = (float*)p;
    cudaGetSymbolAddress(&p, d_smlp); float* smlp = (float*)p;

    const int NB_NODE = (NN + 255) / 256;
    const int NB_EDGE = (NE + 255) / 256;
    const int NB_WARP = (NN * 32 + 255) / 256;
    const int MB = (NN + 127) / 128;   // 391

    static cudaStream_t sMlp = nullptr, sGnn = nullptr;
    static cudaEvent_t evFork = nullptr, evMlp = nullptr, evGemm1 = nullptr, evPrep = nullptr;
    static bool inited = false;
    if (!inited) {
        cudaStreamCreateWithFlags(&sMlp, cudaStreamNonBlocking);
        cudaStreamCreateWithFlags(&sGnn, cudaStreamNonBlocking);
        cudaEventCreateWithFlags(&evFork, cudaEventDisableTiming);
        cudaEventCreateWithFlags(&evMlp, cudaEventDisableTiming);
        cudaEventCreateWithFlags(&evGemm1, cudaEventDisableTiming);
        cudaEventCreateWithFlags(&evPrep, cudaEventDisableTiming);
        cudaFuncSetAttribute(mlp_gemm, cudaFuncAttributeMaxDynamicSharedMemorySize,
                             MLP_SMEM_BYTES);
        cudaFuncSetAttribute(gcn1_gemm, cudaFuncAttributeMaxDynamicSharedMemorySize,
                             G1_SMEM_BYTES);
        inited = true;
    }

    cudaEventRecord(evFork, 0);
    cudaStreamWaitEvent(sGnn, evFork, 0);
    cudaStreamWaitEvent(sMlp, evFork, 0);

    // MLP branch on sMlp
    prep_vecs<<<1, 512, 0, sMlp>>>(fc2W, g2W, fc2b, g2b, fcfW, fcfb);
    cudaEventRecord(evPrep, sMlp);
    cudaMemsetAsync(smlp, 0, NN * sizeof(float), sMlp);

    // GNN transform on sGnn
    gcn1_gemm<<<MB, 256, G1_SMEM_BYTES, sGnn>>>(NN, x, g1W, h1);
    cudaEventRecord(evGemm1, sGnn);

    // preproc head (main)
    init_nodes<<<NB_NODE, 256>>>();

    // MLP GEMM (4th kernel enqueued — ncu target)
    mlp_gemm<<<dim3(4, MB), 256, MLP_SMEM_BYTES, sMlp>>>(NN, uf, fc1W, fc1b, smlp);
    cudaEventRecord(evMlp, sMlp);

    // rest of preprocessing (main)
    edge_deg_count<<<NB_EDGE, 256>>>(src, dst, ea);
    compute_dinv<<<NB_NODE, 256>>>();
    scan_block<<<SCAN_B, SCAN_T>>>();
    scan_top<<<1, 64>>>();
    finalize_rowptr<<<NB_NODE, 256>>>();
    fill_csr<<<NB_EDGE, 256>>>(src, dst, ea);

    // aggregation 1 (+relu, + z-dot); needs h1 and d_vg
    cudaStreamWaitEvent(0, evGemm1, 0);
    cudaStreamWaitEvent(0, evPrep, 0);
    gcn_agg1_z<<<NB_WARP, 256>>>(h1, g1b, z);

    // scalar aggregation 2 + final combine; needs s_mlp
    cudaStreamWaitEvent(0, evMlp, 0);
    gcn_agg2_out<<<NB_WARP, 256>>>(z, smlp, out);
}

// round 8
// speedup vs baseline: 1.9896x; 1.1406x over previous
#include <cuda_runtime.h>
#include <cstdint>
#include <cstddef>

#define NN 50000
#define NE 800000
#define SCAN_T 1024
#define SCAN_B ((NN + SCAN_T - 1) / SCAN_T)   // 49

// ---------------- static device scratch ----------------
__device__ float d_deg[NN];
__device__ float d_dinv[NN];
__device__ int   d_counts[NN];
__device__ int   d_scanned[NN];
__device__ int   d_scanblk[SCAN_B];
__device__ int   d_rowptr[NN + 1];
__device__ int   d_wp[NN];
__device__ int   d_csr_src[NE];
__device__ float d_csr_w[NE];
__device__ float d_h1[NN * 64];
__device__ float d_z[NN];
__device__ float d_smlp[NN];
__device__ float d_w2f[512];   // fc2_W @ fcf_W[0:64]
__device__ float d_vg[64];     // gcn2_W @ fcf_W[64:128]
__device__ float d_cmlp;       // fc2_b . fcf_W[0:64]
__device__ float d_cgnn;       // gcn2_b . fcf_W[64:128] + fcf_b
__device__ float d_w1f[8 * 8 * 4096];   // W1 tf32-rounded, fragment-major tiles [bcol][kt][4096]
__device__ float d_g1f[8 * 2048];       // g1W tf32-rounded, fragment-major tiles [kt][2048]

// ---------------- tf32 helper ----------------
__device__ __forceinline__ uint32_t f2tf32(float f) {
    uint32_t u;
    asm("cvt.rna.tf32.f32 %0, %1;" : "=r"(u) : "f"(f));
    return u;
}

// ---------------- precompute collapsed vectors ----------------
__global__ void prep_vecs(const float* __restrict__ W2, const float* __restrict__ g2W,
                          const float* __restrict__ b2, const float* __restrict__ g2b,
                          const float* __restrict__ Wf, const float* __restrict__ fb) {
    int t = threadIdx.x;   // 512 threads
    float s = 0.f;
#pragma unroll 8
    for (int c = 0; c < 64; c++) s += W2[t * 64 + c] * Wf[c];
    d_w2f[t] = s;
    if (t < 64) {
        float s2 = 0.f;
#pragma unroll 8
        for (int c = 0; c < 64; c++) s2 += g2W[t * 64 + c] * Wf[64 + c];
        d_vg[t] = s2;
    }
    if (t == 0) {
        float cm = 0.f, cg = 0.f;
        for (int c = 0; c < 64; c++) { cm += b2[c] * Wf[c]; cg += g2b[c] * Wf[64 + c]; }
        d_cmlp = cm;
        d_cgnn = cg + fb[0];
    }
}

// ---------------- fragment-major weight packing ----------------
// mlp B tile (bcol,kt): 4096 words. word = (q*32+lane)*4 + j, q = ks*8+wn*4+ntp,
//   j: ntodd=j>>1, r=j&1. value = W1[kt*32+ks*8+t+r*4][bcol*128+(wn*8+ntp*2+ntodd)*8+g]
__global__ void prep_w1f(const float* __restrict__ W1) {
    int idx = blockIdx.x * blockDim.x + threadIdx.x;
    if (idx >= 8 * 8 * 4096) return;
    int tile = idx >> 12, w = idx & 4095;
    int bcol = tile >> 3, kt = tile & 7;
    int q = w >> 7, lane = (w >> 2) & 31, j = w & 3;
    int ks = q >> 3, wn = (q >> 2) & 1, ntp = q & 3;
    int g = lane >> 2, t = lane & 3, ntodd = j >> 1, r = j & 1;
    int k = kt * 32 + ks * 8 + t + r * 4;
    int n = bcol * 128 + (wn * 8 + ntp * 2 + ntodd) * 8 + g;
    d_w1f[idx] = __uint_as_float(f2tf32(W1[(size_t)k * 512 + n]));
}

// gcn1 B tile (kt): 2048 words. q = ks*4+wn*2+ntp (ntp 0..1)
__global__ void prep_g1f(const float* __restrict__ B) {
    int idx = blockIdx.x * blockDim.x + threadIdx.x;
    if (idx >= 8 * 2048) return;
    int kt = idx >> 11, w = idx & 2047;
    int q = w >> 7, lane = (w >> 2) & 31, j = w & 3;
    int ks = q >> 2, wn = (q >> 1) & 1, ntp = q & 1;
    int g = lane >> 2, t = lane & 3, ntodd = j >> 1, r = j & 1;
    int k = kt * 32 + ks * 8 + t + r * 4;
    int n = (wn * 4 + ntp * 2 + ntodd) * 8 + g;
    d_g1f[idx] = __uint_as_float(f2tf32(B[(size_t)k * 64 + n]));
}

// ---------------- graph preprocessing ----------------
__global__ void init_nodes() {
    int i = blockIdx.x * blockDim.x + threadIdx.x;
    if (i < NN) { d_deg[i] = 1.0f; d_counts[i] = 0; }
}

__global__ void edge_deg_count(const int* __restrict__ src, const int* __restrict__ dst,
                               const float* __restrict__ ew) {
    int e = blockIdx.x * blockDim.x + threadIdx.x;
    if (e < NE) {
        int d = dst[e];
        atomicAdd(&d_deg[d], ew[e]);
        atomicAdd(&d_counts[d], 1);
    }
}

__global__ void compute_dinv() {
    int i = blockIdx.x * blockDim.x + threadIdx.x;
    if (i < NN) {
        float dg = d_deg[i];
        d_dinv[i] = (dg > 0.0f) ? rsqrtf(fmaxf(dg, 1e-12f)) : 0.0f;
    }
}

__global__ void scan_block() {
    __shared__ int s[SCAN_T];
    int tid = threadIdx.x;
    int i = blockIdx.x * SCAN_T + tid;
    int v = (i < NN) ? d_counts[i] : 0;
    s[tid] = v;
    __syncthreads();
#pragma unroll
    for (int off = 1; off < SCAN_T; off <<= 1) {
        int t = (tid >= off) ? s[tid - off] : 0;
        __syncthreads();
        s[tid] += t;
        __syncthreads();
    }
    if (i < NN) d_scanned[i] = s[tid];
    if (tid == SCAN_T - 1) d_scanblk[blockIdx.x] = s[tid];
}

__global__ void scan_top() {
    __shared__ int s[64];
    int tid = threadIdx.x;
    int v = (tid < SCAN_B) ? d_scanblk[tid] : 0;
    s[tid] = v;
    __syncthreads();
#pragma unroll
    for (int off = 1; off < 64; off <<= 1) {
        int t = (tid >= off) ? s[tid - off] : 0;
        __syncthreads();
        s[tid] += t;
        __syncthreads();
    }
    if (tid < SCAN_B) d_scanblk[tid] = (tid == 0) ? 0 : s[tid - 1];
}

__global__ void finalize_rowptr() {
    int i = blockIdx.x * blockDim.x + threadIdx.x;
    if (i < NN) {
        int incl = d_scanned[i] + d_scanblk[i >> 10];
        d_rowptr[i + 1] = incl;
        int excl = (i == 0) ? 0 : (d_scanned[i - 1] + d_scanblk[(i - 1) >> 10]);
        d_wp[i] = excl;
        if (i == 0) d_rowptr[0] = 0;
    }
}

__global__ void fill_csr(const int* __restrict__ src, const int* __restrict__ dst,
                         const float* __restrict__ ew) {
    int e = blockIdx.x * blockDim.x + threadIdx.x;
    if (e < NE) {
        int s = src[e];
        int d = dst[e];
        int pos = atomicAdd(&d_wp[d], 1);
        d_csr_src[pos] = s;
        d_csr_w[pos] = d_dinv[s] * ew[e] * d_dinv[d];
    }
}

// ---------------- GCN aggregation 1 + relu + z = g . vg ----------------
__global__ void gcn_agg1_z(const float* __restrict__ h, const float* __restrict__ bias,
                           float* __restrict__ z) {
    int gw = (blockIdx.x * blockDim.x + threadIdx.x) >> 5;
    int lane = threadIdx.x & 31;
    if (gw >= NN) return;
    int i = gw;
    float di = d_dinv[i];
    float selfw = di * di;
    float a0 = selfw * h[(size_t)i * 64 + lane];
    float a1 = selfw * h[(size_t)i * 64 + 32 + lane];
    int beg = d_rowptr[i];
    int end = d_rowptr[i + 1];
    int j = beg;
    for (; j + 2 <= end; j += 2) {
        int s0 = d_csr_src[j], s1 = d_csr_src[j + 1];
        float w0 = d_csr_w[j], w1 = d_csr_w[j + 1];
        float v00 = h[(size_t)s0 * 64 + lane];
        float v01 = h[(size_t)s0 * 64 + 32 + lane];
        float v10 = h[(size_t)s1 * 64 + lane];
        float v11 = h[(size_t)s1 * 64 + 32 + lane];
        a0 += w0 * v00 + w1 * v10;
        a1 += w0 * v01 + w1 * v11;
    }
    if (j < end) {
        int s = d_csr_src[j];
        float w = d_csr_w[j];
        a0 += w * h[(size_t)s * 64 + lane];
        a1 += w * h[(size_t)s * 64 + 32 + lane];
    }
    a0 = fmaxf(a0 + bias[lane], 0.0f);
    a1 = fmaxf(a1 + bias[32 + lane], 0.0f);
    float zi = a0 * d_vg[lane] + a1 * d_vg[32 + lane];
#pragma unroll
    for (int off = 16; off > 0; off >>= 1)
        zi += __shfl_down_sync(0xFFFFFFFFu, zi, off);
    if (lane == 0) z[i] = zi;
}

// ---------------- scalar aggregation 2 + final combine ----------------
__global__ void gcn_agg2_out(const float* __restrict__ z, const float* __restrict__ smlp,
                             float* __restrict__ out) {
    int gw = (blockIdx.x * blockDim.x + threadIdx.x) >> 5;
    int lane = threadIdx.x & 31;
    if (gw >= NN) return;
    int i = gw;
    float di = d_dinv[i];
    float acc = (lane == 0) ? di * di * z[i] : 0.0f;
    int beg = d_rowptr[i];
    int end = d_rowptr[i + 1];
    for (int j = beg + lane; j < end; j += 32)
        acc += d_csr_w[j] * z[d_csr_src[j]];
#pragma unroll
    for (int off = 16; off > 0; off >>= 1)
        acc += __shfl_down_sync(0xFFFFFFFFu, acc, off);
    if (lane == 0) out[i] = acc + smlp[i] + d_cmlp + d_cgnn;
}

// ---------------- mma / cp.async helpers ----------------
__device__ __forceinline__ void mma_tf32(float c[4], uint4 a, uint2 b) {
    asm volatile(
        "mma.sync.aligned.m16n8k8.row.col.f32.tf32.tf32.f32 "
        "{%0,%1,%2,%3},{%4,%5,%6,%7},{%8,%9},{%0,%1,%2,%3};\n"
        : "+f"(c[0]), "+f"(c[1]), "+f"(c[2]), "+f"(c[3])
        : "r"(a.x), "r"(a.y), "r"(a.z), "r"(a.w), "r"(b.x), "r"(b.y));
}

__device__ __forceinline__ uint32_t smem_u32(const void* p) {
    return (uint32_t)__cvta_generic_to_shared(p);
}
__device__ __forceinline__ void cp16(uint32_t dst, const void* src) {
    asm volatile("cp.async.cg.shared.global [%0], [%1], 16;" :: "r"(dst), "l"(src));
}
#define CP_COMMIT() asm volatile("cp.async.commit_group;" ::: "memory")
#define CP_WAIT(n)  asm volatile("cp.async.wait_group %0;" :: "n"(n) : "memory")

// A smem layout: row-major + XOR swizzle, word = row*32 + (k ^ ((row&7)<<2))
// B smem: fragment-major (packed offline), LDS.128 per nt-pair, conflict-free.

// ---------------- MLP GEMM: s_mlp[row] += relu(uf@W1+b1)[row,:] . w2f ----------------
// BM=128, BN=128, BK=32, 3-stage cp.async, grid (4, 391), 256 thr (4wm x 2wn, warp 32x64)
#define MLP_SMEM_BYTES ((3 * 4096 + 3 * 4096 + 128) * 4)

__global__ __launch_bounds__(256, 2) void mlp_gemm(
    int M, const float* __restrict__ A,
    const float* __restrict__ b1, float* __restrict__ s_mlp) {

    extern __shared__ float sm[];
    float* sA = sm;                // 3 x 4096
    float* sB = sm + 3 * 4096;     // 3 x 4096
    float* sRed = sm + 6 * 4096;   // 128

    const int tid = threadIdx.x, brow = blockIdx.y, bcol = blockIdx.x;
    const int w = tid >> 5, lane = tid & 31, wm = w & 3, wn = w >> 2;
    const int g = lane >> 2, t = lane & 3;
    const int swA = g << 2;
    if (tid < 128) sRed[tid] = 0.f;

    const uint32_t sAu = smem_u32(sA), sBu = smem_u32(sB);
    const float* w1tile = d_w1f + (size_t)bcol * 8 * 4096;

    auto issue = [&](int kt, int s) {
#pragma unroll
        for (int i = 0; i < 4; i++) {
            int idx = tid + i * 256;
            int row = idx >> 3, c = idx & 7;
            int grow = brow * 128 + row; if (grow >= M) grow = M - 1;
            uint32_t dst = sAu + (uint32_t)(s * 4096 + row * 32 + ((c ^ (row & 7)) << 2)) * 4u;
            cp16(dst, &A[(size_t)grow * 256 + kt * 32 + c * 4]);
        }
#pragma unroll
        for (int i = 0; i < 4; i++) {
            int widx = (tid + i * 256) * 4;
            uint32_t dst = sBu + (uint32_t)(s * 4096 + widx) * 4u;
            cp16(dst, &w1tile[kt * 4096 + widx]);
        }
        CP_COMMIT();
    };

    float acc[2][8][4] = {};

    issue(0, 0);
    issue(1, 1);
#pragma unroll
    for (int kt = 0; kt < 8; kt++) {
        if (kt == 7) { CP_WAIT(0); } else { CP_WAIT(1); }
        __syncthreads();
        const float* bA = sA + (kt % 3) * 4096;
        const uint4* bB4 = (const uint4*)(sB + (kt % 3) * 4096);
#pragma unroll
        for (int ks = 0; ks < 4; ks++) {
            const int kb = ks * 8;
            uint4 a[2];
#pragma unroll
            for (int mt = 0; mt < 2; mt++) {
                int r0 = wm * 32 + mt * 16 + g;
                int r1 = r0 + 8;
                a[mt].x = f2tf32(bA[r0 * 32 + ((kb + t) ^ swA)]);
                a[mt].y = f2tf32(bA[r1 * 32 + ((kb + t) ^ swA)]);
                a[mt].z = f2tf32(bA[r0 * 32 + ((kb + t + 4) ^ swA)]);
                a[mt].w = f2tf32(bA[r1 * 32 + ((kb + t + 4) ^ swA)]);
            }
#pragma unroll
            for (int ntp = 0; ntp < 4; ntp++) {
                uint4 bb = bB4[(ks * 8 + wn * 4 + ntp) * 32 + lane];
                uint2 b0 = make_uint2(bb.x, bb.y);
                uint2 b1v = make_uint2(bb.z, bb.w);
                mma_tf32(acc[0][ntp * 2], a[0], b0);
                mma_tf32(acc[1][ntp * 2], a[1], b0);
                mma_tf32(acc[0][ntp * 2 + 1], a[0], b1v);
                mma_tf32(acc[1][ntp * 2 + 1], a[1], b1v);
            }
        }
        if (kt < 6) issue(kt + 2, (kt + 2) % 3);
    }

    // epilogue: relu + dot with w2f
    float p[2][2] = {{0.f, 0.f}, {0.f, 0.f}};
#pragma unroll
    for (int nt = 0; nt < 8; nt++) {
        int gcol = bcol * 128 + wn * 64 + nt * 8 + t * 2;
        float bb0 = b1[gcol], bb1 = b1[gcol + 1];
        float w0 = d_w2f[gcol], w1 = d_w2f[gcol + 1];
#pragma unroll
        for (int mt = 0; mt < 2; mt++) {
            p[mt][0] += fmaxf(acc[mt][nt][0] + bb0, 0.f) * w0 + fmaxf(acc[mt][nt][1] + bb1, 0.f) * w1;
            p[mt][1] += fmaxf(acc[mt][nt][2] + bb0, 0.f) * w0 + fmaxf(acc[mt][nt][3] + bb1, 0.f) * w1;
        }
    }
#pragma unroll
    for (int off = 1; off <= 2; off <<= 1) {
        p[0][0] += __shfl_xor_sync(0xFFFFFFFFu, p[0][0], off);
        p[0][1] += __shfl_xor_sync(0xFFFFFFFFu, p[0][1], off);
        p[1][0] += __shfl_xor_sync(0xFFFFFFFFu, p[1][0], off);
        p[1][1] += __shfl_xor_sync(0xFFFFFFFFu, p[1][1], off);
    }
    if (t == 0) {
#pragma unroll
        for (int mt = 0; mt < 2; mt++) {
            int r0 = wm * 32 + mt * 16 + g;
            atomicAdd(&sRed[r0], p[mt][0]);
            atomicAdd(&sRed[r0 + 8], p[mt][1]);
        }
    }
    __syncthreads();
    if (tid < 128) {
        int grow = brow * 128 + tid;
        if (grow < M) atomicAdd(&s_mlp[grow], sRed[tid]);
    }
}

// ---------------- GCN1 transform: h1 = x @ g1W ----------------
#define G1_SMEM_BYTES ((3 * 4096 + 3 * 2048) * 4)

__global__ __launch_bounds__(256, 2) void gcn1_gemm(
    int M, const float* __restrict__ A, float* __restrict__ C) {

    extern __shared__ float sm[];
    float* sA = sm;                // 3 x 4096
    float* sB = sm + 3 * 4096;     // 3 x 2048

    const int tid = threadIdx.x, brow = blockIdx.x;
    const int w = tid >> 5, lane = tid & 31, wm = w & 3, wn = w >> 2;
    const int g = lane >> 2, t = lane & 3;
    const int swA = g << 2;

    const uint32_t sAu = smem_u32(sA), sBu = smem_u32(sB);

    auto issue = [&](int kt, int s) {
#pragma unroll
        for (int i = 0; i < 4; i++) {
            int idx = tid + i * 256;
            int row = idx >> 3, c = idx & 7;
            int grow = brow * 128 + row; if (grow >= M) grow = M - 1;
            uint32_t dst = sAu + (uint32_t)(s * 4096 + row * 32 + ((c ^ (row & 7)) << 2)) * 4u;
            cp16(dst, &A[(size_t)grow * 256 + kt * 32 + c * 4]);
        }
#pragma unroll
        for (int i = 0; i < 2; i++) {
            int widx = (tid + i * 256) * 4;
            uint32_t dst = sBu + (uint32_t)(s * 2048 + widx) * 4u;
            cp16(dst, &d_g1f[kt * 2048 + widx]);
        }
        CP_COMMIT();
    };

    float acc[2][4][4] = {};

    issue(0, 0);
    issue(1, 1);
#pragma unroll
    for (int kt = 0; kt < 8; kt++) {
        if (kt == 7) { CP_WAIT(0); } else { CP_WAIT(1); }
        __syncthreads();
        const float* bA = sA + (kt % 3) * 4096;
        const uint4* bB4 = (const uint4*)(sB + (kt % 3) * 2048);
#pragma unroll
        for (int ks = 0; ks < 4; ks++) {
            const int kb = ks * 8;
            uint4 a[2];
#pragma unroll
            for (int mt = 0; mt < 2; mt++) {
                int r0 = wm * 32 + mt * 16 + g;
                int r1 = r0 + 8;
                a[mt].x = f2tf32(bA[r0 * 32 + ((kb + t) ^ swA)]);
                a[mt].y = f2tf32(bA[r1 * 32 + ((kb + t) ^ swA)]);
                a[mt].z = f2tf32(bA[r0 * 32 + ((kb + t + 4) ^ swA)]);
                a[mt].w = f2tf32(bA[r1 * 32 + ((kb + t + 4) ^ swA)]);
            }
#pragma unroll
            for (int ntp = 0; ntp < 2; ntp++) {
                uint4 bb = bB4[(ks * 4 + wn * 2 + ntp) * 32 + lane];
                uint2 b0 = make_uint2(bb.x, bb.y);
                uint2 b1v = make_uint2(bb.z, bb.w);
                mma_tf32(acc[0][ntp * 2], a[0], b0);
                mma_tf32(acc[1][ntp * 2], a[1], b0);
                mma_tf32(acc[0][ntp * 2 + 1], a[0], b1v);
                mma_tf32(acc[1][ntp * 2 + 1], a[1], b1v);
            }
        }
        if (kt < 6) issue(kt + 2, (kt + 2) % 3);
    }

#pragma unroll
    for (int mt = 0; mt < 2; mt++) {
#pragma unroll
        for (int nt = 0; nt < 4; nt++) {
            int gcol = wn * 32 + nt * 8 + t * 2;
            int grow0 = brow * 128 + wm * 32 + mt * 16 + g;
            if (grow0 < M)
                *(float2*)&C[(size_t)grow0 * 64 + gcol] = make_float2(acc[mt][nt][0], acc[mt][nt][1]);
            if (grow0 + 8 < M)
                *(float2*)&C[(size_t)(grow0 + 8) * 64 + gcol] = make_float2(acc[mt][nt][2], acc[mt][nt][3]);
        }
    }
}

// ---------------- launch ----------------
extern "C" void kernel_launch(void* const* d_in, const int* in_sizes, int n_in,
                              void* d_out, int out_size) {
    const float* x     = (const float*)d_in[0];
    const int*   ei    = (const int*)d_in[1];
    const float* ea    = (const float*)d_in[2];
    const float* uf    = (const float*)d_in[3];
    const float* g1W   = (const float*)d_in[4];
    const float* g1b   = (const float*)d_in[5];
    const float* g2W   = (const float*)d_in[6];
    const float* g2b   = (const float*)d_in[7];
    const float* fc1W  = (const float*)d_in[8];
    const float* fc1b  = (const float*)d_in[9];
    const float* fc2W  = (const float*)d_in[10];
    const float* fc2b  = (const float*)d_in[11];
    const float* fcfW  = (const float*)d_in[12];
    const float* fcfb  = (const float*)d_in[13];
    float* out = (float*)d_out;

    const int* src = ei;
    const int* dst = ei + NE;

    void* p;
    cudaGetSymbolAddress(&p, d_h1);   float* h1   = (float*)p;
    cudaGetSymbolAddress(&p, d_z);    float* z    = (float*)p;
    cudaGetSymbolAddress(&p, d_smlp); float* smlp = (float*)p;

    const int NB_NODE = (NN + 255) / 256;
    const int NB_EDGE = (NE + 255) / 256;
    const int NB_WARP = (NN * 32 + 255) / 256;
    const int MB = (NN + 127) / 128;   // 391

    static cudaStream_t sMlp = nullptr, sGnn = nullptr;
    static cudaEvent_t evFork = nullptr, evMlp = nullptr, evGemm1 = nullptr, evPrep = nullptr;
    static bool inited = false;
    if (!inited) {
        cudaStreamCreateWithFlags(&sMlp, cudaStreamNonBlocking);
        cudaStreamCreateWithFlags(&sGnn, cudaStreamNonBlocking);
        cudaEventCreateWithFlags(&evFork, cudaEventDisableTiming);
        cudaEventCreateWithFlags(&evMlp, cudaEventDisableTiming);
        cudaEventCreateWithFlags(&evGemm1, cudaEventDisableTiming);
        cudaEventCreateWithFlags(&evPrep, cudaEventDisableTiming);
        cudaFuncSetAttribute(mlp_gemm, cudaFuncAttributeMaxDynamicSharedMemorySize,
                             MLP_SMEM_BYTES);
        cudaFuncSetAttribute(gcn1_gemm, cudaFuncAttributeMaxDynamicSharedMemorySize,
                             G1_SMEM_BYTES);
        inited = true;
    }

    cudaEventRecord(evFork, 0);
    cudaStreamWaitEvent(sGnn, evFork, 0);
    cudaStreamWaitEvent(sMlp, evFork, 0);

    // MLP branch on sMlp: collapsed vectors + packed W1, then GEMM
    prep_vecs<<<1, 512, 0, sMlp>>>(fc2W, g2W, fc2b, g2b, fcfW, fcfb);
    cudaEventRecord(evPrep, sMlp);
    prep_w1f<<<(8 * 8 * 4096 + 255) / 256, 256, 0, sMlp>>>(fc1W);
    cudaMemsetAsync(smlp, 0, NN * sizeof(float), sMlp);

    // GNN transform on sGnn: packed g1W, then GEMM
    prep_g1f<<<(8 * 2048 + 255) / 256, 256, 0, sGnn>>>(g1W);
    gcn1_gemm<<<MB, 256, G1_SMEM_BYTES, sGnn>>>(NN, x, h1);
    cudaEventRecord(evGemm1, sGnn);

    // preproc head (main)
    init_nodes<<<NB_NODE, 256>>>();

    // MLP GEMM
    mlp_gemm<<<dim3(4, MB), 256, MLP_SMEM_BYTES, sMlp>>>(NN, uf, fc1b, smlp);
    cudaEventRecord(evMlp, sMlp);

    // rest of preprocessing (main)
    edge_deg_count<<<NB_EDGE, 256>>>(src, dst, ea);
    compute_dinv<<<NB_NODE, 256>>>();
    scan_block<<<SCAN_B, SCAN_T>>>();
    scan_top<<<1, 64>>>();
    finalize_rowptr<<<NB_NODE, 256>>>();
    fill_csr<<<NB_EDGE, 256>>>(src, dst, ea);

    // aggregation 1 (+relu, + z-dot); needs h1 and d_vg
    cudaStreamWaitEvent(0, evGemm1, 0);
    cudaStreamWaitEvent(0, evPrep, 0);
    gcn_agg1_z<<<NB_WARP, 256>>>(h1, g1b, z);

    // scalar aggregation 2 + final combine; needs s_mlp
    cudaStreamWaitEvent(0, evMlp, 0);
    gcn_agg2_out<<<NB_WARP, 256>>>(z, smlp, out);
}